// round 7
// baseline (speedup 1.0000x reference)
#include <cuda_runtime.h>
#include <cuda_fp16.h>

#define BATCH    128
#define NPTS     16384
#define GL       48
#define GW       20
#define GH       18
#define SLAB     (GL * GW * GH)        // 17280 voxels; half2 pair slab = 69120 B
#define HALF_L   2.4f
#define HALF_W   1.0f

#define BLOCKS_PER_BATCH 4
#define THREADS          512
#define PTS_PER_BLOCK    (NPTS / BLOCKS_PER_BATCH)     // 4096
#define GROUPS           (PTS_PER_BLOCK / (THREADS*4)) // 2

#define SMEM_BYTES (SLAB * 4)          // SLAB half2 entries

__global__ __launch_bounds__(THREADS, 3)
void pose_loss_kernel(const float* __restrict__ voxels,
                      const float* __restrict__ pts,
                      const float* __restrict__ hgt,
                      float* __restrict__ out)
{
    extern __shared__ __half2 svox[];  // z-pair table: svox[i] = (v[i], v[i+1 or same if z==17])

    const int batch = blockIdx.x / BLOCKS_PER_BATCH;
    const int chunk = blockIdx.x % BLOCKS_PER_BATCH;
    const int tid   = threadIdx.x;

    // ---- prefetch group-0 streaming data (hides DRAM latency under staging) ----
    const size_t gp0 = (size_t)batch * NPTS + chunk * PTS_PER_BLOCK + tid * 4;
    const float4* __restrict__ pf0 = (const float4*)(pts + gp0 * 3);
    float4 A = pf0[0], Bv = pf0[1], C = pf0[2];
    float4 H = *(const float4*)(hgt + gp0);

    // ---- stage z-pair slab into shared ----
    {
        const float* __restrict__ vsrc = voxels + (size_t)batch * SLAB;
        for (int i = tid; i < SLAB / 4; i += THREADS) {
            const int i4 = i * 4;
            const float4 a = *(const float4*)(vsrc + i4);
            int nidx = i4 + 4; if (nidx >= SLAB) nidx = SLAB - 1;
            const float nxt = vsrc[nidx];
            // pair partner for element at linear idx: next element, unless z==17
            // z(idx)==17  <=>  (idx+1) % 18 == 0
            const int m = (i4 + 1) % GH;   // cond_k: m == (18-k)%18
            const float n0 = (m == 0)  ? a.x : a.y;
            const float n1 = (m == 17) ? a.y : a.z;
            const float n2 = (m == 16) ? a.z : a.w;
            const float n3 = (m == 15) ? a.w : nxt;
            svox[i4 + 0] = __floats2half2_rn(a.x, n0);
            svox[i4 + 1] = __floats2half2_rn(a.y, n1);
            svox[i4 + 2] = __floats2half2_rn(a.z, n2);
            svox[i4 + 3] = __floats2half2_rn(a.w, n3);
        }
    }
    __syncthreads();

    float acc = 0.0f;

    #pragma unroll
    for (int j = 0; j < GROUPS; ++j) {
        // prefetch next group before computing this one
        float4 An, Bn, Cn, Hn;
        if (j + 1 < GROUPS) {
            const size_t gpn = gp0 + (size_t)(j + 1) * (THREADS * 4);
            const float4* __restrict__ pfn = (const float4*)(pts + gpn * 3);
            An = pfn[0]; Bn = pfn[1]; Cn = pfn[2];
            Hn = *(const float4*)(hgt + gpn);
        }

        const float PX[4] = { A.x, A.w, Bv.z, C.y };
        const float PY[4] = { A.y, Bv.x, Bv.w, C.z };
        const float PZ[4] = { A.z, Bv.y, C.x, C.w };
        const float HH[4] = { H.x, H.y, H.z, H.w };

        #pragma unroll
        for (int k = 0; k < 4; ++k) {
            const float x = PX[k] + HALF_L;
            const float y = PY[k] + HALF_W;
            const float z = PZ[k] + HH[k] * 0.5f;

            const int ix = __float2int_rd(x * 10.0f);
            const int iy = __float2int_rd(y * 10.0f);
            const int iz = __float2int_rd(z * 10.0f);

            // t = (l+1)/2 folded: t = (x - xm*0.1)*10   (exact to 1 ULP of ref)
            const float tx = (x - (float)ix * 0.1f) * 10.0f;
            const float ty = (y - (float)iy * 0.1f) * 10.0f;
            const float tz = (z - (float)iz * 0.1f) * 10.0f;

            // clamped indices; lower-clamp handled by zeroing t (exact vs ref)
            const int x0 = min(max(ix, 0), GL - 1);
            const int y0 = min(max(iy, 0), GW - 1);
            const int zp = min(max(iz, 0), GH - 1);
            const int x1 = min(x0 + 1, GL - 1);
            const int y1 = min(y0 + 1, GW - 1);

            const float txp = (ix < 0) ? 0.0f : tx;
            const float typ = (iy < 0) ? 0.0f : ty;
            const float tzp = (iz < 0) ? 0.0f : tz;
            const float sxp = 1.0f - txp;
            const float syp = 1.0f - typ;
            const float szp = 1.0f - tzp;

            const int r0 = x0 * GW, r1 = x1 * GW;
            const int c00 = (r0 + y0) * GH + zp;
            const int c01 = (r0 + y1) * GH + zp;
            const int c10 = (r1 + y0) * GH + zp;
            const int c11 = (r1 + y1) * GH + zp;

            const float2 f00 = __half22float2(svox[c00]);
            const float2 f01 = __half22float2(svox[c01]);
            const float2 f10 = __half22float2(svox[c10]);
            const float2 f11 = __half22float2(svox[c11]);

            // z-blend each (x,y) corner, then bilinear in x,y
            const float v00 = fmaf(f00.y, tzp, f00.x * szp);
            const float v01 = fmaf(f01.y, tzp, f01.x * szp);
            const float v10 = fmaf(f10.y, tzp, f10.x * szp);
            const float v11 = fmaf(f11.y, tzp, f11.x * szp);

            const float vx1 = fmaf(v11, typ, v10 * syp);
            const float vx0 = fmaf(v01, typ, v00 * syp);
            const float sdf = fmaf(vx1, txp, vx0 * sxp);

            const float ax = fabsf(sdf);
            acc += (ax < 1.0f) ? (0.5f * sdf * sdf) : (ax - 0.5f);
        }

        A = An; Bv = Bn; C = Cn; H = Hn;
    }

    // ---- block reduction ----
    #pragma unroll
    for (int off = 16; off > 0; off >>= 1)
        acc += __shfl_xor_sync(0xFFFFFFFFu, acc, off);

    __shared__ float warp_sums[THREADS / 32];
    const int lane = tid & 31;
    const int wid  = tid >> 5;
    if (lane == 0) warp_sums[wid] = acc;
    __syncthreads();

    if (wid == 0) {
        float s = (lane < THREADS / 32) ? warp_sums[lane] : 0.0f;
        #pragma unroll
        for (int off = 8; off > 0; off >>= 1)
            s += __shfl_xor_sync(0xFFFFFFFFu, s, off);
        if (lane == 0)
            atomicAdd(out, s * (1.0f / ((float)BATCH * (float)NPTS)));
    }
}

extern "C" void kernel_launch(void* const* d_in, const int* in_sizes, int n_in,
                              void* d_out, int out_size)
{
    const float* voxels = (const float*)d_in[0];
    const float* pts    = (const float*)d_in[1];
    const float* hgt    = (const float*)d_in[2];
    float* out          = (float*)d_out;

    static int configured = 0;
    if (!configured) {
        cudaFuncSetAttribute(pose_loss_kernel,
                             cudaFuncAttributeMaxDynamicSharedMemorySize,
                             SMEM_BYTES);
        configured = 1;
    }

    cudaMemsetAsync(out, 0, sizeof(float));

    const int grid = BATCH * BLOCKS_PER_BATCH;   // 512 CTAs
    pose_loss_kernel<<<grid, THREADS, SMEM_BYTES>>>(voxels, pts, hgt, out);
}